// round 12
// baseline (speedup 1.0000x reference)
#include <cuda_runtime.h>
#include <cuda_fp16.h>
#include <cstdint>

#define N_NODES       100000
#define IN_F          32
#define OUT_F         64
#define K_TOT         25
#define MAX_DEG       96          /* Poisson(16): observed max ~36; 96 is ultra-safe */
#define NODES_PER_BLK 64
#define HS_STRIDE     804         /* floats; 804 % 32 == 4 -> conflict-free frag reads */
#define THREADS       512
#define BS_NSTRIDE    20          /* words per n-row of a W chunk (fragment order) */
#define BS_CHUNK      (64 * BS_NSTRIDE)   /* 1280 words per kc chunk */

// Per-node cursors, bucketed 16B edge records (basis precomputed), fp16 weights
// pre-packed in mma-fragment order: g_Whalf[kc][n][kword] (kword 0..15 data, 16..19 pad).
__device__ int g_cnt[N_NODES];
__device__ __align__(16) float4   g_rec[(size_t)N_NODES * MAX_DEG];
__device__ __align__(16) uint32_t g_Whalf[K_TOT * BS_CHUNK];

// ---------------------------------------------------------------------------
// Prep: zero per-node counters AND build fragment-ordered fp16 W.
__global__ void prep_kernel(const float* __restrict__ Wt) {
    int i = blockIdx.x * blockDim.x + threadIdx.x;
    if (i < N_NODES) g_cnt[i] = 0;
    if (i < K_TOT * BS_CHUNK) {
        int kc = i / BS_CHUNK;
        int r  = i % BS_CHUNK;
        int n  = r / BS_NSTRIDE;
        int kw = r % BS_NSTRIDE;
        uint32_t v = 0;
        if (kw < 16) {
            int k = kc * 32 + kw * 2;
            __half h0 = __float2half_rn(Wt[(size_t)k       * OUT_F + n]);
            __half h1 = __float2half_rn(Wt[(size_t)(k + 1) * OUT_F + n]);
            v = (uint32_t)__half_as_ushort(h0) |
                ((uint32_t)__half_as_ushort(h1) << 16);
        }
        g_Whalf[i] = v;
    }
}

// ---------------------------------------------------------------------------
// Bucket edges by destination node; precompute spline basis + kernel bin.
// rec = { col | bin<<17 , b00, b01, b10 }   (b11 = 1 - b00 - b01 - b10)
__global__ void bucket_kernel(const int* __restrict__ ei,
                              const float2* __restrict__ ps, int E) {
    int e = blockIdx.x * blockDim.x + threadIdx.x;
    if (e >= E) return;
    int row = ei[e];
    int col = ei[E + e];
    float2 p = ps[e];
    float v0 = p.x * 4.0f, v1 = p.y * 4.0f;
    int i0 = (int)v0; i0 = i0 < 0 ? 0 : (i0 > 3 ? 3 : i0);
    int i1 = (int)v1; i1 = i1 < 0 ? 0 : (i1 > 3 ? 3 : i1);
    float f0 = v0 - (float)i0, f1 = v1 - (float)i1;
    float g0 = 1.0f - f0,      g1 = 1.0f - f1;
    int bin = i0 * 5 + i1;
    uint32_t u = (uint32_t)col | ((uint32_t)bin << 17);
    int pos = atomicAdd(&g_cnt[row], 1);
    if (pos < MAX_DEG)
        g_rec[(size_t)row * MAX_DEG + pos] =
            make_float4(__uint_as_float(u), g0 * g1, g0 * f1, f0 * g1);
}

// ---------------------------------------------------------------------------
// Fused: champion smem fp32 accumulation (64 x 800) -> in-place fp16 pack ->
// ONE __syncthreads -> barrier-free fp16 m16n8k16 GEMM with B fragments
// register-prefetched one kc ahead from fragment-ordered global W.
__global__ void __launch_bounds__(THREADS)
fused_kernel(const float* __restrict__ feat,   // [N,32]
             const float* __restrict__ bias,   // [64]
             float*       __restrict__ out) {  // [N,64]
    extern __shared__ float sm[];
    float* Hs = sm;                            // 64 x 804 fp32

    const int tid   = threadIdx.x;
    const int lane  = tid & 31;
    const int warp  = tid >> 5;
    const int nbase = blockIdx.x * NODES_PER_BLK;

    // --- zero H tile ---
    for (int i = tid; i < NODES_PER_BLK * HS_STRIDE / 4; i += THREADS)
        ((float4*)Hs)[i] = make_float4(0.f, 0.f, 0.f, 0.f);
    __syncthreads();

    // --- accumulation: warp w exclusively owns local rows [w*4, w*4+4) ---
    // (byte-identical to the 255.6us champion)
    for (int ln = warp * 4; ln < warp * 4 + 4; ln++) {
        int n = nbase + ln;
        if (n >= N_NODES) continue;
        int c = g_cnt[n];
        if (c > MAX_DEG) c = MAX_DEG;
        if (c == 0) continue;
        const float4* __restrict__ rec = &g_rec[(size_t)n * MAX_DEG];
        float* __restrict__ hrow = Hs + ln * HS_STRIDE;

        float4 rc[4];
        float  xv[4];
#pragma unroll
        for (int q = 0; q < 4; q++) rc[q] = rec[min(q, c - 1)];
#pragma unroll
        for (int q = 0; q < 4; q++) {
            int cq = (int)(__float_as_uint(rc[q].x) & 0x1FFFFu);
            xv[q] = feat[cq * IN_F + lane];
        }
        for (int base = 0; base < c; base += 4) {
            float4 rn[4];
            const int nb = base + 4;
            if (nb < c) {
#pragma unroll
                for (int q = 0; q < 4; q++) rn[q] = rec[min(nb + q, c - 1)];
            }
#pragma unroll
            for (int q = 0; q < 4; q++) {
                if (base + q < c) {
                    uint32_t u = __float_as_uint(rc[q].x);
                    int kb = (int)(u >> 17) * IN_F + lane;
                    float b00 = rc[q].y, b01 = rc[q].z, b10 = rc[q].w;
                    float b11 = 1.0f - b00 - b01 - b10;
                    float x = xv[q];
                    hrow[kb            ] += b00 * x;
                    hrow[kb +     IN_F ] += b01 * x;
                    hrow[kb + 5 * IN_F ] += b10 * x;
                    hrow[kb + 6 * IN_F ] += b11 * x;
                }
            }
            if (nb < c) {
#pragma unroll
                for (int q = 0; q < 4; q++) {
                    rc[q] = rn[q];
                    int cq = (int)(__float_as_uint(rc[q].x) & 0x1FFFFu);
                    xv[q] = feat[cq * IN_F + lane];
                }
            }
        }
    }

    // --- in-place fp16 pack of own rows (warp-private) ---
    for (int ln = warp * 4; ln < warp * 4 + 4; ln++) {
        float* hrow = Hs + ln * HS_STRIDE;
        float v[25];
#pragma unroll
        for (int r = 0; r < 25; r++) v[r] = hrow[r * 32 + lane];
        __syncwarp();
        __half* hp = (__half*)hrow;
#pragma unroll
        for (int r = 0; r < 25; r++) hp[r * 32 + lane] = __float2half_rn(v[r]);
    }

    __syncthreads();   // the ONLY block barrier: packed H visible to all warps

    // --- barrier-free fp16 TC GEMM, B register-prefetched one kc ahead ---
    const int a_r    = lane >> 2;   // 0..7
    const int a_c    = lane & 3;    // 0..3
    const int stripe = warp & 3;    // 16-row stripe
    const int quar   = warp >> 2;   // 16-col quarter

    const uint32_t* arow0 = (const uint32_t*)Hs + (stripe * 16 + a_r) * HS_STRIDE;
    const uint32_t* arow1 = arow0 + 8 * HS_STRIDE;
    const uint32_t* bn0   = g_Whalf + (quar * 16     + a_r) * BS_NSTRIDE;  // j=0 rows
    const uint32_t* bn1   = g_Whalf + (quar * 16 + 8 + a_r) * BS_NSTRIDE;  // j=1 rows

    float acc[2][4];
#pragma unroll
    for (int j = 0; j < 2; j++)
#pragma unroll
        for (int q = 0; q < 4; q++) acc[j][q] = 0.f;

    // prefetch B fragments for kc = 0
    uint32_t bcur[8], bnxt[8];
#pragma unroll
    for (int ks = 0; ks < 2; ks++) {
        bcur[ks * 4 + 0] = __ldg(bn0 + ks * 8 + a_c);
        bcur[ks * 4 + 1] = __ldg(bn0 + ks * 8 + a_c + 4);
        bcur[ks * 4 + 2] = __ldg(bn1 + ks * 8 + a_c);
        bcur[ks * 4 + 3] = __ldg(bn1 + ks * 8 + a_c + 4);
    }

    for (int kc = 0; kc < K_TOT; kc++) {
        if (kc + 1 < K_TOT) {     // issue next chunk's loads; consumed next iter
            int off = (kc + 1) * BS_CHUNK;
#pragma unroll
            for (int ks = 0; ks < 2; ks++) {
                bnxt[ks * 4 + 0] = __ldg(bn0 + off + ks * 8 + a_c);
                bnxt[ks * 4 + 1] = __ldg(bn0 + off + ks * 8 + a_c + 4);
                bnxt[ks * 4 + 2] = __ldg(bn1 + off + ks * 8 + a_c);
                bnxt[ks * 4 + 3] = __ldg(bn1 + off + ks * 8 + a_c + 4);
            }
        }
#pragma unroll
        for (int ks = 0; ks < 2; ks++) {
            int abase = kc * 16 + ks * 8 + a_c;
            uint32_t a0 = arow0[abase];
            uint32_t a1 = arow1[abase];
            uint32_t a2 = arow0[abase + 4];
            uint32_t a3 = arow1[abase + 4];
            asm volatile(
                "mma.sync.aligned.m16n8k16.row.col.f32.f16.f16.f32 "
                "{%0,%1,%2,%3}, {%4,%5,%6,%7}, {%8,%9}, {%0,%1,%2,%3};\n"
                : "+f"(acc[0][0]), "+f"(acc[0][1]), "+f"(acc[0][2]), "+f"(acc[0][3])
                : "r"(a0), "r"(a1), "r"(a2), "r"(a3),
                  "r"(bcur[ks * 4 + 0]), "r"(bcur[ks * 4 + 1]));
            asm volatile(
                "mma.sync.aligned.m16n8k16.row.col.f32.f16.f16.f32 "
                "{%0,%1,%2,%3}, {%4,%5,%6,%7}, {%8,%9}, {%0,%1,%2,%3};\n"
                : "+f"(acc[1][0]), "+f"(acc[1][1]), "+f"(acc[1][2]), "+f"(acc[1][3])
                : "r"(a0), "r"(a1), "r"(a2), "r"(a3),
                  "r"(bcur[ks * 4 + 2]), "r"(bcur[ks * 4 + 3]));
        }
#pragma unroll
        for (int q = 0; q < 8; q++) bcur[q] = bnxt[q];
    }

    // --- epilogue ---
    int r0 = nbase + stripe * 16 + a_r;
    int r1 = r0 + 8;
#pragma unroll
    for (int j = 0; j < 2; j++) {
        int c = quar * 16 + j * 8 + a_c * 2;
        float bv0 = bias[c], bv1 = bias[c + 1];
        if (r0 < N_NODES)
            *(float2*)(out + (size_t)r0 * OUT_F + c) =
                make_float2(acc[j][0] + bv0, acc[j][1] + bv1);
        if (r1 < N_NODES)
            *(float2*)(out + (size_t)r1 * OUT_F + c) =
                make_float2(acc[j][2] + bv0, acc[j][3] + bv1);
    }
}

// ---------------------------------------------------------------------------
extern "C" void kernel_launch(void* const* d_in, const int* in_sizes, int n_in,
                              void* d_out, int out_size) {
    const float*  feat   = (const float*) d_in[0];
    const float2* pseudo = (const float2*)d_in[1];
    const int*    ei     = (const int*)   d_in[2];
    const float*  Wt     = (const float*) d_in[3];
    const float*  bias   = (const float*) d_in[4];
    float*        out    = (float*)       d_out;

    const int E = in_sizes[1] / 2;

    const int smem_bytes = NODES_PER_BLK * HS_STRIDE * 4;   // 205,824
    cudaFuncSetAttribute(fused_kernel, cudaFuncAttributeMaxDynamicSharedMemorySize,
                         smem_bytes);

    prep_kernel<<<(N_NODES + 255) / 256, 256>>>(Wt);
    bucket_kernel<<<(E + 255) / 256, 256>>>(ei, pseudo, E);
    fused_kernel<<<(N_NODES + NODES_PER_BLK - 1) / NODES_PER_BLK, THREADS, smem_bytes>>>(
        feat, bias, out);
}

// round 13
// speedup vs baseline: 1.1849x; 1.1849x over previous
#include <cuda_runtime.h>
#include <cuda_fp16.h>
#include <cstdint>

#define N_NODES       100000
#define IN_F          32
#define OUT_F         64
#define K_TOT         25
#define MAX_DEG       96          /* Poisson(16): observed max ~36; 96 is ultra-safe */
#define NODES_PER_BLK 64
#define HS_STRIDE     804         /* floats; 804 % 32 == 4 -> conflict-free frag reads */
#define THREADS       512
#define NWARP         16
#define BS_NSTRIDE    20          /* words per n-row of a staged B chunk; CF reads */
#define BS_CHUNK      (64 * BS_NSTRIDE)   /* 1280 words = 5120 B per kc chunk */

// Per-node cursors, bucketed 16B edge records (basis precomputed), fp16 weights
// pre-packed in mma-fragment order: g_Whalf[kc][n][kword] (kword 0..15 data, 16..19 pad).
__device__ int g_cnt[N_NODES];
__device__ __align__(16) float4   g_rec[(size_t)N_NODES * MAX_DEG];
__device__ __align__(16) uint32_t g_Whalf[K_TOT * BS_CHUNK];

// ---------------------------------------------------------------------------
// Prep: zero per-node counters AND build fragment-ordered fp16 W.
__global__ void prep_kernel(const float* __restrict__ Wt) {
    int i = blockIdx.x * blockDim.x + threadIdx.x;
    if (i < N_NODES) g_cnt[i] = 0;
    if (i < K_TOT * BS_CHUNK) {
        int kc = i / BS_CHUNK;
        int r  = i % BS_CHUNK;
        int n  = r / BS_NSTRIDE;
        int kw = r % BS_NSTRIDE;
        uint32_t v = 0;
        if (kw < 16) {
            int k = kc * 32 + kw * 2;
            __half h0 = __float2half_rn(Wt[(size_t)k       * OUT_F + n]);
            __half h1 = __float2half_rn(Wt[(size_t)(k + 1) * OUT_F + n]);
            v = (uint32_t)__half_as_ushort(h0) |
                ((uint32_t)__half_as_ushort(h1) << 16);
        }
        g_Whalf[i] = v;
    }
}

// ---------------------------------------------------------------------------
// Bucket edges by destination node; precompute spline basis + kernel bin.
// rec = { col | bin<<17 , b00, b01, b10 }   (b11 = 1 - b00 - b01 - b10)
__global__ void bucket_kernel(const int* __restrict__ ei,
                              const float2* __restrict__ ps, int E) {
    int e = blockIdx.x * blockDim.x + threadIdx.x;
    if (e >= E) return;
    int row = ei[e];
    int col = ei[E + e];
    float2 p = ps[e];
    float v0 = p.x * 4.0f, v1 = p.y * 4.0f;
    int i0 = (int)v0; i0 = i0 < 0 ? 0 : (i0 > 3 ? 3 : i0);
    int i1 = (int)v1; i1 = i1 < 0 ? 0 : (i1 > 3 ? 3 : i1);
    float f0 = v0 - (float)i0, f1 = v1 - (float)i1;
    float g0 = 1.0f - f0,      g1 = 1.0f - f1;
    int bin = i0 * 5 + i1;
    uint32_t u = (uint32_t)col | ((uint32_t)bin << 17);
    int pos = atomicAdd(&g_cnt[row], 1);
    if (pos < MAX_DEG)
        g_rec[(size_t)row * MAX_DEG + pos] =
            make_float4(__uint_as_float(u), g0 * g1, g0 * f1, f0 * g1);
}

// ---------------------------------------------------------------------------
// Fused: champion structure; accumulate uses ONE coalesced record burst per
// node into smem scratch (lane i fetches rec[i]), then broadcast-LDS records
// + the champion's 4-deep feat pipeline. No global stores in the loop.
__global__ void __launch_bounds__(THREADS)
fused_kernel(const float* __restrict__ feat,   // [N,32]
             const float* __restrict__ bias,   // [64]
             float*       __restrict__ out) {  // [N,64]
    extern __shared__ float sm[];
    float*    Hs  = sm;                                          // 64 x 804 fp32
    uint32_t* Bsm = (uint32_t*)(sm + NODES_PER_BLK * HS_STRIDE); // 2 x 1280 words
    float4*   Scr = (float4*)(Bsm + 2 * BS_CHUNK);               // 16 warps x 32 recs

    const int tid   = threadIdx.x;
    const int lane  = tid & 31;
    const int warp  = tid >> 5;
    const int nbase = blockIdx.x * NODES_PER_BLK;

    float4* scr = Scr + warp * 32;

    // prefetch first W chunk; lands during accumulation
    uint4 wreg;
    if (tid < BS_CHUNK / 4)
        wreg = ((const uint4*)g_Whalf)[tid];

    // --- zero H tile (block-wide, champion layout) ---
    for (int i = tid; i < NODES_PER_BLK * HS_STRIDE / 4; i += THREADS)
        ((float4*)Hs)[i] = make_float4(0.f, 0.f, 0.f, 0.f);
    __syncthreads();

    // --- accumulation: warp w exclusively owns local rows [w*4, w*4+4) ---
    for (int ln = warp * 4; ln < warp * 4 + 4; ln++) {
        int n = nbase + ln;
        if (n >= N_NODES) continue;
        int c = g_cnt[n];
        if (c > MAX_DEG) c = MAX_DEG;
        if (c == 0) continue;
        const float4* __restrict__ rec = &g_rec[(size_t)n * MAX_DEG];
        float* __restrict__ hrow = Hs + ln * HS_STRIDE;

        // ONE coalesced burst: lane i fetches record i (4 x 128B lines, MLP=4)
        int csc = c < 32 ? c : 32;
        if (lane < csc) scr[lane] = rec[lane];
        __syncwarp();

        // champion 4-deep feat pipeline; records now read via cheap LDS
        float4 rc[4];
        float  xv[4];
#pragma unroll
        for (int q = 0; q < 4; q++) rc[q] = scr[min(q, csc - 1)];
#pragma unroll
        for (int q = 0; q < 4; q++) {
            int cq = (int)(__float_as_uint(rc[q].x) & 0x1FFFFu);
            xv[q] = feat[cq * IN_F + lane];
        }
        for (int base = 0; base < csc; base += 4) {
            float4 rn[4];
            const int nb = base + 4;
            if (nb < csc) {
#pragma unroll
                for (int q = 0; q < 4; q++) rn[q] = scr[min(nb + q, csc - 1)];
            }
#pragma unroll
            for (int q = 0; q < 4; q++) {
                if (base + q < csc) {
                    uint32_t u = __float_as_uint(rc[q].x);
                    int kb = (int)(u >> 17) * IN_F + lane;
                    float b00 = rc[q].y, b01 = rc[q].z, b10 = rc[q].w;
                    float b11 = 1.0f - b00 - b01 - b10;
                    float x = xv[q];
                    hrow[kb            ] += b00 * x;
                    hrow[kb +     IN_F ] += b01 * x;
                    hrow[kb + 5 * IN_F ] += b10 * x;
                    hrow[kb + 6 * IN_F ] += b11 * x;
                }
            }
            if (nb < csc) {
#pragma unroll
                for (int q = 0; q < 4; q++) {
                    rc[q] = rn[q];
                    int cq = (int)(__float_as_uint(rc[q].x) & 0x1FFFFu);
                    xv[q] = feat[cq * IN_F + lane];
                }
            }
        }

        // ultra-rare tail (deg > 32): direct broadcast loads
        for (int j = 32; j < c; j++) {
            float4 r = rec[j];
            uint32_t u = __float_as_uint(r.x);
            int cq = (int)(u & 0x1FFFFu);
            float x = feat[cq * IN_F + lane];
            int kb = (int)(u >> 17) * IN_F + lane;
            float b00 = r.y, b01 = r.z, b10 = r.w;
            float b11 = 1.0f - b00 - b01 - b10;
            hrow[kb            ] += b00 * x;
            hrow[kb +     IN_F ] += b01 * x;
            hrow[kb + 5 * IN_F ] += b10 * x;
            hrow[kb + 6 * IN_F ] += b11 * x;
        }
        __syncwarp();   // scratch reuse safety for next node
    }

    // --- in-place fp16 pack of own rows (warp-private, champion code) ---
    for (int ln = warp * 4; ln < warp * 4 + 4; ln++) {
        float* hrow = Hs + ln * HS_STRIDE;
        float v[25];
#pragma unroll
        for (int r = 0; r < 25; r++) v[r] = hrow[r * 32 + lane];
        __syncwarp();
        __half* hp = (__half*)hrow;
#pragma unroll
        for (int r = 0; r < 25; r++) hp[r * 32 + lane] = __float2half_rn(v[r]);
    }

    // stage B chunk 0 into buffer 0
    if (tid < BS_CHUNK / 4)
        ((uint4*)Bsm)[tid] = wreg;
    __syncthreads();   // covers pack visibility + Bs0

    // --- fp16 TC GEMM (champion, double-buffered B) ---
    const int a_r    = lane >> 2;   // 0..7
    const int a_c    = lane & 3;    // 0..3
    const int stripe = warp & 3;    // 16-row stripe
    const int quar   = warp >> 2;   // 16-col quarter

    const uint32_t* arow0 = (const uint32_t*)Hs + (stripe * 16 + a_r) * HS_STRIDE;
    const uint32_t* arow1 = arow0 + 8 * HS_STRIDE;

    float acc[2][4];
#pragma unroll
    for (int j = 0; j < 2; j++)
#pragma unroll
        for (int q = 0; q < 4; q++) acc[j][q] = 0.f;

    for (int kc = 0; kc < K_TOT; kc++) {
        const uint32_t* Bcur = Bsm + (kc & 1) * BS_CHUNK;
        uint4 wnext;
        const bool more = (kc + 1 < K_TOT) && (tid < BS_CHUNK / 4);
        if (more)
            wnext = ((const uint4*)(g_Whalf + (kc + 1) * BS_CHUNK))[tid];

#pragma unroll
        for (int ks = 0; ks < 2; ks++) {
            int abase = kc * 16 + ks * 8 + a_c;
            uint32_t a0 = arow0[abase];
            uint32_t a1 = arow1[abase];
            uint32_t a2 = arow0[abase + 4];
            uint32_t a3 = arow1[abase + 4];
#pragma unroll
            for (int j = 0; j < 2; j++) {
                const uint32_t* bn = Bcur + (quar * 16 + j * 8 + a_r) * BS_NSTRIDE;
                uint32_t b0 = bn[ks * 8 + a_c];
                uint32_t b1 = bn[ks * 8 + a_c + 4];
                asm volatile(
                    "mma.sync.aligned.m16n8k16.row.col.f32.f16.f16.f32 "
                    "{%0,%1,%2,%3}, {%4,%5,%6,%7}, {%8,%9}, {%0,%1,%2,%3};\n"
                    : "+f"(acc[j][0]), "+f"(acc[j][1]),
                      "+f"(acc[j][2]), "+f"(acc[j][3])
                    : "r"(a0), "r"(a1), "r"(a2), "r"(a3), "r"(b0), "r"(b1));
            }
        }
        if (more)
            ((uint4*)(Bsm + ((kc + 1) & 1) * BS_CHUNK))[tid] = wnext;
        __syncthreads();
    }

    // --- epilogue ---
    int r0 = nbase + stripe * 16 + a_r;
    int r1 = r0 + 8;
#pragma unroll
    for (int j = 0; j < 2; j++) {
        int c = quar * 16 + j * 8 + a_c * 2;
        float bv0 = bias[c], bv1 = bias[c + 1];
        if (r0 < N_NODES)
            *(float2*)(out + (size_t)r0 * OUT_F + c) =
                make_float2(acc[j][0] + bv0, acc[j][1] + bv1);
        if (r1 < N_NODES)
            *(float2*)(out + (size_t)r1 * OUT_F + c) =
                make_float2(acc[j][2] + bv0, acc[j][3] + bv1);
    }
}

// ---------------------------------------------------------------------------
extern "C" void kernel_launch(void* const* d_in, const int* in_sizes, int n_in,
                              void* d_out, int out_size) {
    const float*  feat   = (const float*) d_in[0];
    const float2* pseudo = (const float2*)d_in[1];
    const int*    ei     = (const int*)   d_in[2];
    const float*  Wt     = (const float*) d_in[3];
    const float*  bias   = (const float*) d_in[4];
    float*        out    = (float*)       d_out;

    const int E = in_sizes[1] / 2;

    // Hs 205,824 + B 10,240 + scratch 8,192 = 224,256 B (within 227 KB opt-in)
    const int smem_bytes = NODES_PER_BLK * HS_STRIDE * 4 + 2 * BS_CHUNK * 4
                         + NWARP * 32 * 16;
    cudaFuncSetAttribute(fused_kernel, cudaFuncAttributeMaxDynamicSharedMemorySize,
                         smem_bytes);

    prep_kernel<<<(N_NODES + 255) / 256, 256>>>(Wt);
    bucket_kernel<<<(E + 255) / 256, 256>>>(ei, pseudo, E);
    fused_kernel<<<(N_NODES + NODES_PER_BLK - 1) / NODES_PER_BLK, THREADS, smem_bytes>>>(
        feat, bias, out);
}